// round 6
// baseline (speedup 1.0000x reference)
#include <cuda_runtime.h>

#define NN 100000
#define EE 5000000
#define TOT (NN * 16)

// ---------------- scratch (device globals; no allocations allowed) ----------
__device__ __align__(128) float g_agg[TOT];   // aggregation accumulator
__device__ __align__(128) float g_s[TOT];     // pre-BN sums
__device__ __align__(128) float g_h0[TOT];    // layer-1 output
__device__ __align__(128) float g_h1[TOT];    // layer-2 output
__device__ float g_sum[16];
__device__ float g_sq[16];
__device__ float g_scale[16];
__device__ float g_shift[16];

// ---------------- init: zero agg (N*8 floats used by layer 1) + stats -------
__global__ void k_zero_init() {
    int i = blockIdx.x * blockDim.x + threadIdx.x;
    if (i < NN * 2)  // N*8 floats = N*2 float4
        reinterpret_cast<float4*>(g_agg)[i] = make_float4(0.f, 0.f, 0.f, 0.f);
    if (i < 16) { g_sum[i] = 0.f; g_sq[i] = 0.f; }
}

// ---------------- edge aggregation: agg[dst] += x[src] ----------------------
// SRC: 0 = param pointer (layer-1 input x), 1 = g_h0, 2 = g_h1
template <int F, int SRC>
__global__ void k_agg(const float* __restrict__ xp, const int* __restrict__ ei) {
    int e = blockIdx.x * blockDim.x + threadIdx.x;
    if (e >= EE) return;
    const float* __restrict__ x = (SRC == 0) ? xp : (SRC == 1 ? g_h0 : g_h1);
    int src = __ldg(ei + e);
    int dst = __ldg(ei + EE + e);
    const float4* xs = reinterpret_cast<const float4*>(x + (size_t)src * F);
    float* ad = g_agg + (size_t)dst * F;
#pragma unroll
    for (int v = 0; v < F / 4; v++) {
        float4 val = __ldg(xs + v);
        asm volatile("red.global.add.v4.f32 [%0], {%1,%2,%3,%4};"
                     :: "l"(ad + 4 * v), "f"(val.x), "f"(val.y), "f"(val.z), "f"(val.w)
                     : "memory");
    }
}

// ---------------- dense: GIN MLP + residual + BN stats ----------------------
// s = mlp2(act(mlp1((1+eps)*x + agg))) + (x @ rw + rb); accumulate sum/sumsq
template <int FIN, bool LEAKY, int SRC>
__global__ void k_dense(const float* __restrict__ xp, const float* __restrict__ epsp,
                        const float* __restrict__ w1, const float* __restrict__ b1,
                        const float* __restrict__ w2, const float* __restrict__ b2,
                        const float* __restrict__ rw, const float* __restrict__ rb) {
    __shared__ float sw1[FIN * 16], srw[FIN * 16], sw2[256];
    __shared__ float sb1[16], sb2[16], srb[16];
    __shared__ float ssum[16], ssq[16];
    __shared__ float seps;
    int t = threadIdx.x;
    for (int i = t; i < FIN * 16; i += blockDim.x) { sw1[i] = w1[i]; srw[i] = rw[i]; }
    for (int i = t; i < 256; i += blockDim.x) sw2[i] = w2[i];
    if (t < 16) { sb1[t] = b1[t]; sb2[t] = b2[t]; srb[t] = rb[t]; ssum[t] = 0.f; ssq[t] = 0.f; }
    if (t == 0) seps = 1.0f + *epsp;
    __syncthreads();

    const float* __restrict__ xin = (SRC == 0) ? xp : (SRC == 1 ? g_h0 : g_h1);
    int node = blockIdx.x * blockDim.x + t;
    float s[16];
    if (node < NN) {
        float xv[FIN], tv[FIN];
        const float4* xr = reinterpret_cast<const float4*>(xin + (size_t)node * FIN);
        const float4* ar = reinterpret_cast<const float4*>(g_agg + (size_t)node * FIN);
#pragma unroll
        for (int v = 0; v < FIN / 4; v++) {
            float4 a = __ldg(xr + v);
            float4 g = ar[v];
            xv[4 * v + 0] = a.x; xv[4 * v + 1] = a.y; xv[4 * v + 2] = a.z; xv[4 * v + 3] = a.w;
            tv[4 * v + 0] = seps * a.x + g.x;
            tv[4 * v + 1] = seps * a.y + g.y;
            tv[4 * v + 2] = seps * a.z + g.z;
            tv[4 * v + 3] = seps * a.w + g.w;
        }
        float h1[16];
#pragma unroll
        for (int o = 0; o < 16; o++) {
            float a = sb1[o];
#pragma unroll
            for (int i = 0; i < FIN; i++) a = fmaf(tv[i], sw1[i * 16 + o], a);
            h1[o] = LEAKY ? (a > 0.f ? a : 0.01f * a) : fmaxf(a, 0.f);
        }
#pragma unroll
        for (int o = 0; o < 16; o++) {
            float a = sb2[o];
#pragma unroll
            for (int i = 0; i < 16; i++) a = fmaf(h1[i], sw2[i * 16 + o], a);
            float r = srb[o];
#pragma unroll
            for (int i = 0; i < FIN; i++) r = fmaf(xv[i], srw[i * 16 + o], r);
            s[o] = a + r;
        }
        float4* sp = reinterpret_cast<float4*>(g_s + (size_t)node * 16);
#pragma unroll
        for (int v = 0; v < 4; v++)
            sp[v] = make_float4(s[4 * v], s[4 * v + 1], s[4 * v + 2], s[4 * v + 3]);
    } else {
#pragma unroll
        for (int o = 0; o < 16; o++) s[o] = 0.f;
    }

    // per-feature warp reduction of sum / sumsq, then smem, then global
#pragma unroll
    for (int o = 0; o < 16; o++) {
        float v = s[o], q = s[o] * s[o];
#pragma unroll
        for (int d = 16; d; d >>= 1) {
            v += __shfl_xor_sync(0xffffffffu, v, d);
            q += __shfl_xor_sync(0xffffffffu, q, d);
        }
        if ((t & 31) == 0) { atomicAdd(&ssum[o], v); atomicAdd(&ssq[o], q); }
    }
    __syncthreads();
    if (t < 16) { atomicAdd(&g_sum[t], ssum[t]); atomicAdd(&g_sq[t], ssq[t]); }
}

// ---------------- BN finalize: scale/shift from accumulated stats -----------
__global__ void k_finalize(const float* __restrict__ g, const float* __restrict__ be) {
    int t = threadIdx.x;
    if (t < 16) {
        float mean = g_sum[t] * (1.0f / NN);
        float var  = g_sq[t] * (1.0f / NN) - mean * mean;
        float sc = g[t] * rsqrtf(var + 1e-5f);
        g_scale[t] = sc;
        g_shift[t] = be[t] - mean * sc;
    }
}

// ---------------- BN apply + zero next agg/stats -----------------------------
// DST: 0 = param pointer (final output), 1 = g_h0, 2 = g_h1
template <int DST>
__global__ void k_apply(float* __restrict__ outp) {
    int i = blockIdx.x * blockDim.x + threadIdx.x;  // over TOT/4 float4s
    if (i < TOT / 4) {
        float* __restrict__ out = (DST == 0) ? outp : (DST == 1 ? g_h0 : g_h1);
        float4 v  = reinterpret_cast<const float4*>(g_s)[i];
        float4 sc = reinterpret_cast<const float4*>(g_scale)[i & 3];
        float4 sh = reinterpret_cast<const float4*>(g_shift)[i & 3];
        v.x = v.x * sc.x + sh.x;
        v.y = v.y * sc.y + sh.y;
        v.z = v.z * sc.z + sh.z;
        v.w = v.w * sc.w + sh.w;
        reinterpret_cast<float4*>(out)[i] = v;
        reinterpret_cast<float4*>(g_agg)[i] = make_float4(0.f, 0.f, 0.f, 0.f);
    }
    if (i < 16) { g_sum[i] = 0.f; g_sq[i] = 0.f; }
}

// ---------------- launch ------------------------------------------------------
extern "C" void kernel_launch(void* const* d_in, const int* in_sizes, int n_in,
                              void* d_out, int out_size) {
    const float* x   = (const float*)d_in[0];
    const int*   ei  = (const int*)d_in[1];
    const float *eps1 = (const float*)d_in[2],  *w11 = (const float*)d_in[3],
                *b11  = (const float*)d_in[4],  *w12 = (const float*)d_in[5],
                *b12  = (const float*)d_in[6],  *rw1 = (const float*)d_in[7],
                *rb1  = (const float*)d_in[8],  *g1  = (const float*)d_in[9],
                *be1  = (const float*)d_in[10];
    const float *eps2 = (const float*)d_in[11], *w21 = (const float*)d_in[12],
                *b21  = (const float*)d_in[13], *w22 = (const float*)d_in[14],
                *b22  = (const float*)d_in[15], *rw2 = (const float*)d_in[16],
                *rb2  = (const float*)d_in[17], *g2  = (const float*)d_in[18],
                *be2  = (const float*)d_in[19];
    const float *eps3 = (const float*)d_in[20], *w31 = (const float*)d_in[21],
                *b31  = (const float*)d_in[22], *w32 = (const float*)d_in[23],
                *b32  = (const float*)d_in[24], *rw3 = (const float*)d_in[25],
                *rb3  = (const float*)d_in[26], *g3  = (const float*)d_in[27],
                *be3  = (const float*)d_in[28];
    float* out = (float*)d_out;

    const int TB = 256;
    dim3 gz((NN * 2 + TB - 1) / TB);
    dim3 ge((EE + TB - 1) / TB);
    dim3 gn((NN + TB - 1) / TB);
    dim3 ga((TOT / 4 + TB - 1) / TB);

    // ---- block 1 (FIN=8, leaky relu) ----
    k_zero_init<<<gz, TB>>>();
    k_agg<8, 0><<<ge, TB>>>(x, ei);
    k_dense<8, true, 0><<<gn, TB>>>(x, eps1, w11, b11, w12, b12, rw1, rb1);
    k_finalize<<<1, 32>>>(g1, be1);
    k_apply<1><<<ga, TB>>>(nullptr);        // -> g_h0, zero agg+stats

    // ---- block 2 (FIN=16, relu) ----
    k_agg<16, 1><<<ge, TB>>>(nullptr, ei);
    k_dense<16, false, 1><<<gn, TB>>>(nullptr, eps2, w21, b21, w22, b22, rw2, rb2);
    k_finalize<<<1, 32>>>(g2, be2);
    k_apply<2><<<ga, TB>>>(nullptr);        // -> g_h1, zero agg+stats

    // ---- block 3 (FIN=16, relu) ----
    k_agg<16, 2><<<ge, TB>>>(nullptr, ei);
    k_dense<16, false, 2><<<gn, TB>>>(nullptr, eps3, w31, b31, w32, b32, rw3, rb3);
    k_finalize<<<1, 32>>>(g3, be3);
    k_apply<0><<<ga, TB>>>(out);            // -> d_out
}

// round 9
// speedup vs baseline: 1.2358x; 1.2358x over previous
#include <cuda_runtime.h>

#define NN 100000
#define EE 5000000
#define TOT (NN * 16)
#define NB_SCAN 98  // ceil(NN/1024)

// ---------------- scratch (device globals; no allocations allowed) ----------
__device__ __align__(128) float    g_s[TOT];     // pre-BN sums
__device__ __align__(128) float    g_h0[TOT];    // layer-1 output
__device__ __align__(128) float    g_h1[TOT];    // layer-2 output
__device__ __align__(128) int      g_perm[EE];   // CSR: src per edge slot
__device__ __align__(128) unsigned g_cnt[NN];    // in-degree
__device__ __align__(128) unsigned g_off[NN];    // block-local exclusive scan
__device__ __align__(128) unsigned g_row[NN + 1];// CSR row starts
__device__ __align__(128) unsigned g_cur[NN];    // placement cursors
__device__ unsigned g_bsum[128];
__device__ unsigned g_bpre[128];
__device__ float g_psum[1024];                   // 64 buckets x 16 features
__device__ float g_psq[1024];
__device__ float g_scale[16];
__device__ float g_shift[16];

// ---------------- init: zero counts + stat buckets ---------------------------
__global__ void k_zero() {
    int i = blockIdx.x * blockDim.x + threadIdx.x;
    if (i < NN) g_cnt[i] = 0u;
    if (i < 1024) { g_psum[i] = 0.f; g_psq[i] = 0.f; }
}

// ---------------- CSR build --------------------------------------------------
__global__ void k_hist(const int* __restrict__ ei) {
    int e = blockIdx.x * blockDim.x + threadIdx.x;
    if (e < EE) atomicAdd(&g_cnt[__ldg(ei + EE + e)], 1u);  // no return -> RED
}

// block-level exclusive scan of g_cnt (1024 per block) + block totals
__global__ void k_scan1() {
    __shared__ unsigned wt[32];
    int t = threadIdx.x;
    int i = blockIdx.x * 1024 + t;
    unsigned v = (i < NN) ? g_cnt[i] : 0u;
    unsigned x = v;
#pragma unroll
    for (int d = 1; d < 32; d <<= 1) {
        unsigned n = __shfl_up_sync(0xffffffffu, x, d);
        if ((t & 31) >= d) x += n;
    }
    if ((t & 31) == 31) wt[t >> 5] = x;
    __syncthreads();
    if (t < 32) {
        unsigned w = wt[t];
        unsigned y = w;
#pragma unroll
        for (int d = 1; d < 32; d <<= 1) {
            unsigned n = __shfl_up_sync(0xffffffffu, y, d);
            if (t >= d) y += n;
        }
        wt[t] = y - w;  // exclusive warp offsets
        if (t == 31) g_bsum[blockIdx.x] = y;  // block total
    }
    __syncthreads();
    if (i < NN) g_off[i] = x - v + wt[t >> 5];
}

// scan 98 block totals (1 block, 128 threads)
__global__ void k_scan2() {
    __shared__ unsigned wt[4];
    int t = threadIdx.x;
    unsigned v = (t < NB_SCAN) ? g_bsum[t] : 0u;
    unsigned x = v;
#pragma unroll
    for (int d = 1; d < 32; d <<= 1) {
        unsigned n = __shfl_up_sync(0xffffffffu, x, d);
        if ((t & 31) >= d) x += n;
    }
    if ((t & 31) == 31) wt[t >> 5] = x;
    __syncthreads();
    unsigned base = 0;
    for (int w = 0; w < (t >> 5); w++) base += wt[w];
    if (t < NB_SCAN) g_bpre[t] = base + x - v;
}

// final row starts + cursors
__global__ void k_row() {
    int i = blockIdx.x * blockDim.x + threadIdx.x;
    if (i < NN) {
        unsigned r = g_off[i] + g_bpre[i >> 10];
        g_row[i] = r;
        g_cur[i] = r;
        if (i == 0) g_row[NN] = EE;
    }
}

__global__ void k_place(const int* __restrict__ ei) {
    int e = blockIdx.x * blockDim.x + threadIdx.x;
    if (e < EE) {
        int dst = __ldg(ei + EE + e);
        unsigned p = atomicAdd(&g_cur[dst], 1u);
        g_perm[p] = __ldg(ei + e);
    }
}

// ---------------- fused: CSR aggregate + GIN MLP + residual + BN stats -------
// warp per node: lane f of each F-group gathers feature f; fold; shfl MLP.
// SRC: 0 = param pointer x, 1 = g_h0, 2 = g_h1
template <int FIN, bool LEAKY, int SRC>
__global__ void __launch_bounds__(256) k_node(
        const float* __restrict__ xp, const float* __restrict__ epsp,
        const float* __restrict__ w1, const float* __restrict__ b1,
        const float* __restrict__ w2, const float* __restrict__ b2,
        const float* __restrict__ rw, const float* __restrict__ rb) {
    __shared__ float sw1[FIN * 16], srw[FIN * 16], sw2[256];
    __shared__ float sb1[16], sb2[16], srb[16];
    __shared__ float ps[16], pq[16];
    __shared__ float seps;
    int t = threadIdx.x;
    for (int i = t; i < FIN * 16; i += 256) { sw1[i] = w1[i]; srw[i] = rw[i]; }
    for (int i = t; i < 256; i += 256) sw2[i] = w2[i];
    if (t < 16) { sb1[t] = b1[t]; sb2[t] = b2[t]; srb[t] = rb[t]; ps[t] = 0.f; pq[t] = 0.f; }
    if (t == 0) seps = 1.0f + *epsp;
    __syncthreads();

    const float* __restrict__ xin = (SRC == 0) ? xp : (SRC == 1 ? g_h0 : g_h1);
    int lane = t & 31;
    int node = blockIdx.x * 8 + (t >> 5);     // grid sized so node < NN always
    int f = lane & (FIN - 1);                 // feature owned in gather phase
    int grp = lane / FIN;                     // edge sub-group within warp
    unsigned row = g_row[node], end = g_row[node + 1];

    float acc = 0.f;
    for (unsigned j = row + grp; j < end; j += 32 / FIN) {
        int src = __ldg(g_perm + j);
        acc += __ldg(xin + (size_t)src * FIN + f);
    }
    // fold edge sub-groups so lanes 0..FIN-1 hold the full aggregate
    acc += __shfl_xor_sync(0xffffffffu, acc, 16);
    if (FIN == 8) acc += __shfl_xor_sync(0xffffffffu, acc, 8);

    float xval = (lane < FIN) ? __ldg(xin + (size_t)node * FIN + lane) : 0.f;
    float tv = seps * xval + acc;             // valid in lanes < FIN

    int o = lane & 15;                        // output feature (lanes 16-31 duplicate)
    float a = sb1[o];
#pragma unroll
    for (int i = 0; i < FIN; i++)
        a = fmaf(__shfl_sync(0xffffffffu, tv, i), sw1[i * 16 + o], a);
    float h1 = LEAKY ? (a > 0.f ? a : 0.01f * a) : fmaxf(a, 0.f);

    float a2 = sb2[o];
#pragma unroll
    for (int i = 0; i < 16; i++)
        a2 = fmaf(__shfl_sync(0xffffffffu, h1, i), sw2[i * 16 + o], a2);
    float r = srb[o];
#pragma unroll
    for (int i = 0; i < FIN; i++)
        r = fmaf(__shfl_sync(0xffffffffu, xval, i), srw[i * 16 + o], r);
    float s = a2 + r;

    if (lane < 16) {
        g_s[(size_t)node * 16 + lane] = s;
        atomicAdd(&ps[lane], s);
        atomicAdd(&pq[lane], s * s);
    }
    __syncthreads();
    if (t < 16) {
        int bkt = (blockIdx.x & 63) * 16 + t;
        atomicAdd(&g_psum[bkt], ps[t]);
        atomicAdd(&g_psq[bkt], pq[t]);
    }
}

// ---------------- BN finalize: reduce buckets, make scale/shift, re-zero -----
__global__ void k_finalize(const float* __restrict__ g, const float* __restrict__ be) {
    int t = threadIdx.x;
    if (t < 16) {
        float s = 0.f, q = 0.f;
#pragma unroll
        for (int b = 0; b < 64; b++) { s += g_psum[b * 16 + t]; q += g_psq[b * 16 + t]; }
        float mean = s * (1.0f / NN);
        float var  = q * (1.0f / NN) - mean * mean;
        float sc = g[t] * rsqrtf(var + 1e-5f);
        g_scale[t] = sc;
        g_shift[t] = be[t] - mean * sc;
    }
    __syncthreads();  // reads done before re-zero
    for (int i = t; i < 1024; i += blockDim.x) { g_psum[i] = 0.f; g_psq[i] = 0.f; }
}

// ---------------- BN apply ----------------------------------------------------
// DST: 0 = d_out, 1 = g_h0, 2 = g_h1
template <int DST>
__global__ void k_apply(float* __restrict__ outp) {
    int i = blockIdx.x * blockDim.x + threadIdx.x;  // over TOT/4 float4s
    if (i < TOT / 4) {
        float* __restrict__ out = (DST == 0) ? outp : (DST == 1 ? g_h0 : g_h1);
        float4 v  = reinterpret_cast<const float4*>(g_s)[i];
        float4 sc = reinterpret_cast<const float4*>(g_scale)[i & 3];
        float4 sh = reinterpret_cast<const float4*>(g_shift)[i & 3];
        v.x = v.x * sc.x + sh.x;
        v.y = v.y * sc.y + sh.y;
        v.z = v.z * sc.z + sh.z;
        v.w = v.w * sc.w + sh.w;
        reinterpret_cast<float4*>(out)[i] = v;
    }
}

// ---------------- launch ------------------------------------------------------
extern "C" void kernel_launch(void* const* d_in, const int* in_sizes, int n_in,
                              void* d_out, int out_size) {
    const float* x   = (const float*)d_in[0];
    const int*   ei  = (const int*)d_in[1];
    const float *eps1 = (const float*)d_in[2],  *w11 = (const float*)d_in[3],
                *b11  = (const float*)d_in[4],  *w12 = (const float*)d_in[5],
                *b12  = (const float*)d_in[6],  *rw1 = (const float*)d_in[7],
                *rb1  = (const float*)d_in[8],  *g1  = (const float*)d_in[9],
                *be1  = (const float*)d_in[10];
    const float *eps2 = (const float*)d_in[11], *w21 = (const float*)d_in[12],
                *b21  = (const float*)d_in[13], *w22 = (const float*)d_in[14],
                *b22  = (const float*)d_in[15], *rw2 = (const float*)d_in[16],
                *rb2  = (const float*)d_in[17], *g2  = (const float*)d_in[18],
                *be2  = (const float*)d_in[19];
    const float *eps3 = (const float*)d_in[20], *w31 = (const float*)d_in[21],
                *b31  = (const float*)d_in[22], *w32 = (const float*)d_in[23],
                *b32  = (const float*)d_in[24], *rw3 = (const float*)d_in[25],
                *rb3  = (const float*)d_in[26], *g3  = (const float*)d_in[27],
                *be3  = (const float*)d_in[28];
    float* out = (float*)d_out;

    const int TB = 256;
    dim3 ge((EE + TB - 1) / TB);
    dim3 gn((NN + TB - 1) / TB);
    dim3 ga((TOT / 4 + TB - 1) / TB);
    dim3 gw(NN / 8);  // 12500 blocks, warp per node (100000 = 12500*8 exactly)

    // ---- CSR build (per call; no caching allowed) ----
    k_zero<<<gn, TB>>>();
    k_hist<<<ge, TB>>>(ei);
    k_scan1<<<NB_SCAN, 1024>>>();
    k_scan2<<<1, 128>>>();
    k_row<<<gn, TB>>>();
    k_place<<<ge, TB>>>(ei);

    // ---- block 1 (FIN=8, leaky relu) ----
    k_node<8, true, 0><<<gw, TB>>>(x, eps1, w11, b11, w12, b12, rw1, rb1);
    k_finalize<<<1, 256>>>(g1, be1);
    k_apply<1><<<ga, TB>>>(nullptr);

    // ---- block 2 (FIN=16, relu) ----
    k_node<16, false, 1><<<gw, TB>>>(nullptr, eps2, w21, b21, w22, b22, rw2, rb2);
    k_finalize<<<1, 256>>>(g2, be2);
    k_apply<2><<<ga, TB>>>(nullptr);

    // ---- block 3 (FIN=16, relu) ----
    k_node<16, false, 2><<<gw, TB>>>(nullptr, eps3, w31, b31, w32, b32, rw3, rb3);
    k_finalize<<<1, 256>>>(g3, be3);
    k_apply<0><<<ga, TB>>>(out);
}